// round 14
// baseline (speedup 1.0000x reference)
#include <cuda_runtime.h>
#include <cuda_fp16.h>
#include <cstdint>

#define NN 200000
#define NE 800000
#define NPAD 200064   // 1563 * 128
#define CHUNK_NODES 25600   // 200 gemm blocks, 3200 agg blocks

// ---------------- device scratch (no allocations allowed) ----------------
__device__ int g_is64;
__device__ int g_mask_mode;  // 0 = byte bool, 1 = int32, 2 = int64
__device__ unsigned int g_flags[3];
__device__ int g_count[NN];
__device__ int g_off[NN + 1];
__device__ int g_cur[NN];
__device__ int g_bsum[256];
__device__ int g_boff[256];
__device__ unsigned int g_sorted[2 * NE];
__device__ __half g_Ahi[(size_t)NPAD * 512];  // 205 MB
__device__ __half g_Bthi[64 * 512];           // basesT fp16 (n-major)

// ---------------- helpers ----------------
__device__ __forceinline__ int ldidx(const int* p, int i, int is64) {
    return is64 ? p[2 * i] : p[i];
}
__device__ __forceinline__ uint32_t smem_u32(const void* p) {
    uint32_t a;
    asm("{ .reg .u64 t; cvta.to.shared.u64 t, %1; cvt.u32.u64 %0, t; }"
        : "=r"(a) : "l"(p));
    return a;
}
__device__ __forceinline__ void ldsm4(uint32_t* r, uint32_t addr) {
    asm volatile("ldmatrix.sync.aligned.m8n8.x4.shared.b16 {%0,%1,%2,%3}, [%4];"
                 : "=r"(r[0]), "=r"(r[1]), "=r"(r[2]), "=r"(r[3]) : "r"(addr));
}
__device__ __forceinline__ void mma16816(float* c, const uint32_t* a,
                                         const uint32_t* b) {
    asm volatile(
        "mma.sync.aligned.m16n8k16.row.col.f32.f16.f16.f32 "
        "{%0,%1,%2,%3}, {%4,%5,%6,%7}, {%8,%9}, {%0,%1,%2,%3};"
        : "+f"(c[0]), "+f"(c[1]), "+f"(c[2]), "+f"(c[3])
        : "r"(a[0]), "r"(a[1]), "r"(a[2]), "r"(a[3]), "r"(b[0]), "r"(b[1]));
}
__device__ __forceinline__ void cp16(uint32_t saddr, const void* gptr) {
    asm volatile("cp.async.cg.shared.global [%0], [%1], 16;"
                 :: "r"(saddr), "l"(gptr) : "memory");
}
#define CP_COMMIT() asm volatile("cp.async.commit_group;" ::: "memory")
#define CP_WAIT(n)  asm volatile("cp.async.wait_group %0;" :: "n"(n) : "memory")

// ---------------- K0a: zero hist + flags ----------------
__global__ void zero_kernel(int N) {
    int i0 = blockIdx.x * blockDim.x + threadIdx.x;
    if (i0 < 3) g_flags[i0] = 0u;
    for (int i = i0; i < N; i += gridDim.x * blockDim.x) g_count[i] = 0;
}

// ---------------- K0b: parallel dtype sniff ----------------
__global__ void sniff_kernel(const unsigned int* idx_words, int n_idx_words,
                             const unsigned int* mask_words, int n_mask) {
    int i0 = blockIdx.x * blockDim.x + threadIdx.x;
    int stride = gridDim.x * blockDim.x;
    unsigned f0 = 0, f1 = 0, f2 = 0;
    for (int i = 1 + 2 * i0; i < n_idx_words; i += 2 * stride)
        f0 |= (idx_words[i] != 0u);
    for (int i = i0; i < n_mask / 4; i += stride)
        f1 |= (mask_words[i] > 1u);
    for (int i = 1 + 2 * i0; i < n_mask / 2; i += 2 * stride)
        f2 |= (mask_words[i] != 0u);
    if (f0) atomicOr(&g_flags[0], 1u);
    if (f1) atomicOr(&g_flags[1], 1u);
    if (f2) atomicOr(&g_flags[2], 1u);
}

__global__ void finalize_sniff_kernel() {
    g_is64 = g_flags[0] ? 0 : 1;
    g_mask_mode = g_flags[1] ? 0 : (g_flags[2] ? 1 : 2);
}

// ---------------- prep: basesT to fp16 ----------------
__global__ void prep_bases_kernel(const float* __restrict__ bases) {
    for (int idx = blockIdx.x * blockDim.x + threadIdx.x; idx < 512 * 64;
         idx += gridDim.x * blockDim.x) {
        int n = idx >> 9, k = idx & 511;
        g_Bthi[n * 512 + k] = __float2half(bases[k * 64 + n]);
    }
}

// ---------------- K2: histogram of edge-direction targets ----------------
__global__ void hist_kernel(const int* src, const int* tgt, int E) {
    int is64 = g_is64;
    for (int i = blockIdx.x * blockDim.x + threadIdx.x; i < 2 * E;
         i += gridDim.x * blockDim.x) {
        int t = (i < E) ? ldidx(tgt, i, is64) : ldidx(src, i - E, is64);
        atomicAdd(&g_count[t], 1);
    }
}

// ---------------- K3: multi-block exclusive scan ----------------
__global__ void scan1_kernel(int N) {
    __shared__ int red[256];
    int b = blockIdx.x, t = threadIdx.x;
    int base = b * 1024 + t * 4;
    int s = 0;
#pragma unroll
    for (int j = 0; j < 4; j++) {
        int idx = base + j;
        if (idx < N) s += g_count[idx];
    }
    red[t] = s;
    __syncthreads();
    for (int off = 128; off > 0; off >>= 1) {
        if (t < off) red[t] += red[t + off];
        __syncthreads();
    }
    if (t == 0) g_bsum[b] = red[0];
}

__global__ void scan2_kernel(int nb, int N) {
    __shared__ int ts[256];
    int t = threadIdx.x;
    int v = (t < nb) ? g_bsum[t] : 0;
    ts[t] = v;
    __syncthreads();
    for (int off = 1; off < 256; off <<= 1) {
        int u = (t >= off) ? ts[t - off] : 0;
        __syncthreads();
        ts[t] += u;
        __syncthreads();
    }
    if (t < nb) g_boff[t] = ts[t] - v;
    if (t == 255) g_off[N] = ts[255];
}

__global__ void scan3_kernel(int N) {
    __shared__ int ts[256];
    int b = blockIdx.x, t = threadIdx.x;
    int base = b * 1024 + t * 4;
    int c[4];
    int s = 0;
#pragma unroll
    for (int j = 0; j < 4; j++) {
        int idx = base + j;
        c[j] = (idx < N) ? g_count[idx] : 0;
        s += c[j];
    }
    ts[t] = s;
    __syncthreads();
    for (int off = 1; off < 256; off <<= 1) {
        int u = (t >= off) ? ts[t - off] : 0;
        __syncthreads();
        ts[t] += u;
        __syncthreads();
    }
    int run = ts[t] - s + g_boff[b];
#pragma unroll
    for (int j = 0; j < 4; j++) {
        int idx = base + j;
        if (idx < N) {
            g_off[idx] = run;
            g_cur[idx] = run;
            run += c[j];
        }
    }
}

// ---------------- K4: scatter edges sorted by target ----------------
__global__ void scatter_kernel(const int* src, const int* tgt, const int* et,
                               int E) {
    int is64 = g_is64;
    for (int i = blockIdx.x * blockDim.x + threadIdx.x; i < 2 * E;
         i += gridDim.x * blockDim.x) {
        int e = (i < E) ? i : i - E;
        int s, t;
        if (i < E) { s = ldidx(src, e, is64); t = ldidx(tgt, e, is64); }
        else       { s = ldidx(tgt, e, is64); t = ldidx(src, e, is64); }
        int r = ldidx(et, e, is64);
        int pos = atomicAdd(&g_cur[t], 1);
        g_sorted[pos] = ((unsigned int)s << 4) | (unsigned int)r;
    }
}

// ---------------- K5: aggregation, warp per node (R9 form), chunked --------
__global__ void agg_kernel(const float* __restrict__ x,
                           const void* __restrict__ mask,
                           const float* __restrict__ att, int N, int base0) {
    __shared__ __align__(16) float4 att_s[34];
    int tid = threadIdx.x;
    if (tid < 34) att_s[tid] = ((const float4*)att)[tid];
    __syncthreads();

    int warp = tid >> 5, lane = tid & 31;
    int n = base0 + blockIdx.x * 8 + warp;
    if (n >= N) return;

    float acc0[8], acc1[8];
#pragma unroll
    for (int b = 0; b < 8; b++) { acc0[b] = 0.f; acc1[b] = 0.f; }

    int beg = g_off[n], end = g_off[n + 1];
    for (int i = beg; i < end; i++) {
        unsigned int p = g_sorted[i];
        int s = (int)(p >> 4);
        int r = (int)(p & 15u);
        float x0 = x[s * 64 + lane];
        float x1 = x[s * 64 + 32 + lane];
        float4 a0 = att_s[r * 2];
        float4 a1 = att_s[r * 2 + 1];
        float ar[8];
        *(float4*)&ar[0] = a0;
        *(float4*)&ar[4] = a1;
#pragma unroll
        for (int b = 0; b < 8; b++) {
            acc0[b] += ar[b] * x0;
            acc1[b] += ar[b] * x1;
        }
    }
    int mm = g_mask_mode;
    int keep;
    if (mm == 0)      keep = ((const unsigned char*)mask)[n];
    else if (mm == 1) keep = ((const int*)mask)[n];
    else              keep = ((const int*)mask)[2 * n];
    if (keep) {
        float x0 = x[n * 64 + lane];
        float x1 = x[n * 64 + 32 + lane];
        float4 a0 = att_s[32];
        float4 a1 = att_s[33];
        float ar[8];
        *(float4*)&ar[0] = a0;
        *(float4*)&ar[4] = a1;
#pragma unroll
        for (int b = 0; b < 8; b++) {
            acc0[b] += ar[b] * x0;
            acc1[b] += ar[b] * x1;
        }
    }
    size_t base = (size_t)n * 512;
#pragma unroll
    for (int b = 0; b < 8; b++) {
        g_Ahi[base + b * 64 + lane]      = __float2half(acc0[b]);
        g_Ahi[base + b * 64 + 32 + lane] = __float2half(acc1[b]);
    }
}

// ---------------- K6: mma.sync fp16 GEMM, double-buffered, chunked ---------
#define OFF_B  0
#define OFF_A0 66560
#define OFF_A1 84992
#define SMEM_MM 103424

__global__ __launch_bounds__(256, 2) void gemm_mm_kernel(
    float* __restrict__ out, int N, int blk0) {
    extern __shared__ __align__(16) char sm[];
    uint32_t sbase = smem_u32(sm);
    int tid = threadIdx.x, wid = tid >> 5, lid = tid & 31;
    int nb = (blk0 + blockIdx.x) * 128;
    int warp_m = (wid & 3) * 32;
    int warp_n = (wid >> 2) * 32;

    // ---- stage B once: 64 rows x 512 k fp16 ----
#pragma unroll
    for (int t = 0; t < 8; t++) {
        int idx = t * 256 + tid;
        int row = idx >> 5;
        int cb = (idx & 31) * 32;
        *(uint4*)(sm + OFF_B + row * 1040 + cb) =
            *(const uint4*)((const char*)g_Bthi + row * 1024 + cb);
        *(uint4*)(sm + OFF_B + row * 1040 + cb + 16) =
            *(const uint4*)((const char*)g_Bthi + row * 1024 + cb + 16);
    }

    auto stageA = [&](int c, uint32_t offA) {
#pragma unroll
        for (int t = 0; t < 2; t++) {
            int idx = t * 256 + tid;
            int row = idx >> 2;
            int cb = (idx & 3) * 32;
            size_t gb = (size_t)(nb + row) * 1024 + (size_t)c * 128 + cb;
            cp16(sbase + offA + row * 144 + cb, (const char*)g_Ahi + gb);
            cp16(sbase + offA + row * 144 + cb + 16, (const char*)g_Ahi + gb + 16);
        }
        CP_COMMIT();
    };

    float acc[2][4][4];
#pragma unroll
    for (int mt = 0; mt < 2; mt++)
#pragma unroll
        for (int nt = 0; nt < 4; nt++)
#pragma unroll
            for (int q = 0; q < 4; q++) acc[mt][nt][q] = 0.f;

    uint32_t a_row0 = (uint32_t)(warp_m + (lid & 15));
    uint32_t a_kb = (uint32_t)(lid & 16);
    uint32_t a_off = a_row0 * 144 + a_kb;
    uint32_t b_row = (uint32_t)(warp_n + (lid & 7) + ((lid >> 4) & 1) * 8);
    uint32_t b_kb = (uint32_t)(((lid >> 3) & 1) * 16);
    uint32_t baddr0 = sbase + OFF_B + b_row * 1040 + b_kb;
    uint32_t baddr1 = baddr0 + 16 * 1040;

    stageA(0, OFF_A0);

    for (int c = 0; c < 8; c++) {
        int cur = c & 1;
        if (c < 7) stageA(c + 1, cur ? OFF_A0 : OFF_A1);
        if (c < 7) CP_WAIT(1); else CP_WAIT(0);
        __syncthreads();

        uint32_t ah0 = sbase + (cur ? OFF_A1 : OFF_A0) + a_off;

#pragma unroll
        for (int ks = 0; ks < 4; ks++) {
            uint32_t kb = (uint32_t)(ks * 32);
            uint32_t gkb = (uint32_t)(c * 128) + kb;
            uint32_t ahi[2][4];
            ldsm4(ahi[0], ah0 + kb);
            ldsm4(ahi[1], ah0 + 16 * 144 + kb);
            uint32_t bhp[2][4];
            ldsm4(bhp[0], baddr0 + gkb);
            ldsm4(bhp[1], baddr1 + gkb);
#pragma unroll
            for (int mt = 0; mt < 2; mt++) {
#pragma unroll
                for (int nt = 0; nt < 4; nt++) {
                    const uint32_t* bf = &bhp[nt >> 1][(nt & 1) * 2];
                    mma16816(acc[mt][nt], ahi[mt], bf);
                }
            }
        }
        __syncthreads();
    }

    int trow = lid >> 2, tcol = (lid & 3) * 2;
#pragma unroll
    for (int mt = 0; mt < 2; mt++) {
        int m0 = nb + warp_m + mt * 16 + trow;
#pragma unroll
        for (int nt = 0; nt < 4; nt++) {
            int col = warp_n + nt * 8 + tcol;
            if (m0 < N)
                *(float2*)(out + (size_t)m0 * 64 + col) =
                    make_float2(acc[mt][nt][0], acc[mt][nt][1]);
            if (m0 + 8 < N)
                *(float2*)(out + (size_t)(m0 + 8) * 64 + col) =
                    make_float2(acc[mt][nt][2], acc[mt][nt][3]);
        }
    }
}

// ---------------- launch ----------------
extern "C" void kernel_launch(void* const* d_in, const int* in_sizes, int n_in,
                              void* d_out, int out_size) {
    const float* x = (const float*)d_in[0];
    const void* mask = d_in[1];
    const int* src = (const int*)d_in[2];
    const int* tgt = (const int*)d_in[3];
    const int* et = (const int*)d_in[4];
    const float* bases = (const float*)d_in[5];
    const float* att = (const float*)d_in[6];
    float* out = (float*)d_out;

    int N = in_sizes[1];
    int E = in_sizes[2];
    int nb = (N + 1023) / 1024;

    cudaFuncSetAttribute(gemm_mm_kernel,
                         cudaFuncAttributeMaxDynamicSharedMemorySize, SMEM_MM);

    zero_kernel<<<256, 256>>>(N);
    sniff_kernel<<<256, 256>>>((const unsigned int*)d_in[2], E,
                               (const unsigned int*)d_in[1], N);
    finalize_sniff_kernel<<<1, 1>>>();
    prep_bases_kernel<<<128, 256>>>(bases);
    hist_kernel<<<3200, 256>>>(src, tgt, E);
    scan1_kernel<<<nb, 256>>>(N);
    scan2_kernel<<<1, 256>>>(nb, N);
    scan3_kernel<<<nb, 256>>>(N);
    scatter_kernel<<<3200, 256>>>(src, tgt, et, E);

    // chunk-interleaved agg/gemm: each 25.6MB A-slice stays L2-resident
    int total_gemm_blocks = (N + 127) / 128;
    for (int base = 0, blk0 = 0; base < N; base += CHUNK_NODES, blk0 += 200) {
        int nodes = (N - base < CHUNK_NODES) ? (N - base) : CHUNK_NODES;
        int ablocks = (nodes + 7) / 8;
        int gblocks = (total_gemm_blocks - blk0 < 200)
                          ? (total_gemm_blocks - blk0) : 200;
        agg_kernel<<<ablocks, 256>>>(x, mask, att, N, base);
        gemm_mm_kernel<<<gblocks, 256, SMEM_MM>>>(out, N, blk0);
    }
}

// round 15
// speedup vs baseline: 1.2607x; 1.2607x over previous
#include <cuda_runtime.h>
#include <cuda_fp16.h>
#include <cstdint>

#define NN 200000
#define NE 800000
#define NPAD 200064   // 1563 * 128

// ---------------- device scratch (no allocations allowed) ----------------
__device__ int g_is64;
__device__ int g_mask_mode;  // 0 = byte bool, 1 = int32, 2 = int64
__device__ unsigned int g_flags[3];
__device__ int g_count[NN];
__device__ int g_off[NN + 1];
__device__ int g_cur[NN];
__device__ int g_bsum[256];
__device__ int g_boff[256];
__device__ unsigned int g_sorted[2 * NE];
__device__ __half g_Ahi[(size_t)NPAD * 512];  // 205 MB
__device__ __half g_Bthi[64 * 512];           // basesT fp16 (n-major, k-contig)

// ---------------- helpers ----------------
__device__ __forceinline__ int ldidx(const int* p, int i, int is64) {
    return is64 ? p[2 * i] : p[i];
}
__device__ __forceinline__ uint32_t smem_u32(const void* p) {
    uint32_t a;
    asm("{ .reg .u64 t; cvta.to.shared.u64 t, %1; cvt.u32.u64 %0, t; }"
        : "=r"(a) : "l"(p));
    return a;
}
__device__ __forceinline__ void ldsm4(uint32_t* r, uint32_t addr) {
    asm volatile("ldmatrix.sync.aligned.m8n8.x4.shared.b16 {%0,%1,%2,%3}, [%4];"
                 : "=r"(r[0]), "=r"(r[1]), "=r"(r[2]), "=r"(r[3]) : "r"(addr));
}
__device__ __forceinline__ void mma16816(float* c, const uint32_t* a,
                                         const uint32_t* b) {
    asm volatile(
        "mma.sync.aligned.m16n8k16.row.col.f32.f16.f16.f32 "
        "{%0,%1,%2,%3}, {%4,%5,%6,%7}, {%8,%9}, {%0,%1,%2,%3};"
        : "+f"(c[0]), "+f"(c[1]), "+f"(c[2]), "+f"(c[3])
        : "r"(a[0]), "r"(a[1]), "r"(a[2]), "r"(a[3]), "r"(b[0]), "r"(b[1]));
}
__device__ __forceinline__ void cp16(uint32_t saddr, const void* gptr) {
    asm volatile("cp.async.cg.shared.global [%0], [%1], 16;"
                 :: "r"(saddr), "l"(gptr) : "memory");
}
#define CP_COMMIT() asm volatile("cp.async.commit_group;" ::: "memory")
#define CP_WAIT(n)  asm volatile("cp.async.wait_group %0;" :: "n"(n) : "memory")

// ---------------- K0a: zero hist + flags ----------------
__global__ void zero_kernel(int N) {
    int i0 = blockIdx.x * blockDim.x + threadIdx.x;
    if (i0 < 3) g_flags[i0] = 0u;
    for (int i = i0; i < N; i += gridDim.x * blockDim.x) g_count[i] = 0;
}

// ---------------- K0b: parallel dtype sniff ----------------
__global__ void sniff_kernel(const unsigned int* idx_words, int n_idx_words,
                             const unsigned int* mask_words, int n_mask) {
    int i0 = blockIdx.x * blockDim.x + threadIdx.x;
    int stride = gridDim.x * blockDim.x;
    unsigned f0 = 0, f1 = 0, f2 = 0;
    for (int i = 1 + 2 * i0; i < n_idx_words; i += 2 * stride)
        f0 |= (idx_words[i] != 0u);
    for (int i = i0; i < n_mask / 4; i += stride)
        f1 |= (mask_words[i] > 1u);
    for (int i = 1 + 2 * i0; i < n_mask / 2; i += 2 * stride)
        f2 |= (mask_words[i] != 0u);
    if (f0) atomicOr(&g_flags[0], 1u);
    if (f1) atomicOr(&g_flags[1], 1u);
    if (f2) atomicOr(&g_flags[2], 1u);
}

__global__ void finalize_sniff_kernel() {
    g_is64 = g_flags[0] ? 0 : 1;
    g_mask_mode = g_flags[1] ? 0 : (g_flags[2] ? 1 : 2);
}

// ---------------- prep: basesT to fp16 ----------------
__global__ void prep_bases_kernel(const float* __restrict__ bases) {
    for (int idx = blockIdx.x * blockDim.x + threadIdx.x; idx < 512 * 64;
         idx += gridDim.x * blockDim.x) {
        int n = idx >> 9, k = idx & 511;
        g_Bthi[n * 512 + k] = __float2half(bases[k * 64 + n]);
    }
}

// ---------------- K2: histogram of edge-direction targets ----------------
__global__ void hist_kernel(const int* src, const int* tgt, int E) {
    int is64 = g_is64;
    for (int i = blockIdx.x * blockDim.x + threadIdx.x; i < 2 * E;
         i += gridDim.x * blockDim.x) {
        int t = (i < E) ? ldidx(tgt, i, is64) : ldidx(src, i - E, is64);
        atomicAdd(&g_count[t], 1);
    }
}

// ---------------- K3: multi-block exclusive scan ----------------
__global__ void scan1_kernel(int N) {
    __shared__ int red[256];
    int b = blockIdx.x, t = threadIdx.x;
    int base = b * 1024 + t * 4;
    int s = 0;
#pragma unroll
    for (int j = 0; j < 4; j++) {
        int idx = base + j;
        if (idx < N) s += g_count[idx];
    }
    red[t] = s;
    __syncthreads();
    for (int off = 128; off > 0; off >>= 1) {
        if (t < off) red[t] += red[t + off];
        __syncthreads();
    }
    if (t == 0) g_bsum[b] = red[0];
}

__global__ void scan2_kernel(int nb, int N) {
    __shared__ int ts[256];
    int t = threadIdx.x;
    int v = (t < nb) ? g_bsum[t] : 0;
    ts[t] = v;
    __syncthreads();
    for (int off = 1; off < 256; off <<= 1) {
        int u = (t >= off) ? ts[t - off] : 0;
        __syncthreads();
        ts[t] += u;
        __syncthreads();
    }
    if (t < nb) g_boff[t] = ts[t] - v;
    if (t == 255) g_off[N] = ts[255];
}

__global__ void scan3_kernel(int N) {
    __shared__ int ts[256];
    int b = blockIdx.x, t = threadIdx.x;
    int base = b * 1024 + t * 4;
    int c[4];
    int s = 0;
#pragma unroll
    for (int j = 0; j < 4; j++) {
        int idx = base + j;
        c[j] = (idx < N) ? g_count[idx] : 0;
        s += c[j];
    }
    ts[t] = s;
    __syncthreads();
    for (int off = 1; off < 256; off <<= 1) {
        int u = (t >= off) ? ts[t - off] : 0;
        __syncthreads();
        ts[t] += u;
        __syncthreads();
    }
    int run = ts[t] - s + g_boff[b];
#pragma unroll
    for (int j = 0; j < 4; j++) {
        int idx = base + j;
        if (idx < N) {
            g_off[idx] = run;
            g_cur[idx] = run;
            run += c[j];
        }
    }
}

// ---------------- K4: scatter edges sorted by target ----------------
__global__ void scatter_kernel(const int* src, const int* tgt, const int* et,
                               int E) {
    int is64 = g_is64;
    for (int i = blockIdx.x * blockDim.x + threadIdx.x; i < 2 * E;
         i += gridDim.x * blockDim.x) {
        int e = (i < E) ? i : i - E;
        int s, t;
        if (i < E) { s = ldidx(src, e, is64); t = ldidx(tgt, e, is64); }
        else       { s = ldidx(tgt, e, is64); t = ldidx(src, e, is64); }
        int r = ldidx(et, e, is64);
        int pos = atomicAdd(&g_cur[t], 1);
        g_sorted[pos] = ((unsigned int)s << 4) | (unsigned int)r;
    }
}

// ---------------- K5: aggregation, warp per node (R9 loop, 512-thr blocks) --
__global__ __launch_bounds__(512) void agg_kernel(
    const float* __restrict__ x, const void* __restrict__ mask,
    const float* __restrict__ att, int N) {
    __shared__ __align__(16) float4 att_s[34];
    int tid = threadIdx.x;
    if (tid < 34) att_s[tid] = ((const float4*)att)[tid];
    __syncthreads();

    int warp = tid >> 5, lane = tid & 31;
    int n = blockIdx.x * 16 + warp;
    if (n >= N) return;

    float acc0[8], acc1[8];
#pragma unroll
    for (int b = 0; b < 8; b++) { acc0[b] = 0.f; acc1[b] = 0.f; }

    int beg = g_off[n], end = g_off[n + 1];
    for (int i = beg; i < end; i++) {
        unsigned int p = g_sorted[i];
        int s = (int)(p >> 4);
        int r = (int)(p & 15u);
        float x0 = x[s * 64 + lane];
        float x1 = x[s * 64 + 32 + lane];
        float4 a0 = att_s[r * 2];
        float4 a1 = att_s[r * 2 + 1];
        float ar[8];
        *(float4*)&ar[0] = a0;
        *(float4*)&ar[4] = a1;
#pragma unroll
        for (int b = 0; b < 8; b++) {
            acc0[b] += ar[b] * x0;
            acc1[b] += ar[b] * x1;
        }
    }
    int mm = g_mask_mode;
    int keep;
    if (mm == 0)      keep = ((const unsigned char*)mask)[n];
    else if (mm == 1) keep = ((const int*)mask)[n];
    else              keep = ((const int*)mask)[2 * n];
    if (keep) {
        float x0 = x[n * 64 + lane];
        float x1 = x[n * 64 + 32 + lane];
        float4 a0 = att_s[32];
        float4 a1 = att_s[33];
        float ar[8];
        *(float4*)&ar[0] = a0;
        *(float4*)&ar[4] = a1;
#pragma unroll
        for (int b = 0; b < 8; b++) {
            acc0[b] += ar[b] * x0;
            acc1[b] += ar[b] * x1;
        }
    }
    size_t base = (size_t)n * 512;
#pragma unroll
    for (int b = 0; b < 8; b++) {
        g_Ahi[base + b * 64 + lane]      = __float2half(acc0[b]);
        g_Ahi[base + b * 64 + 32 + lane] = __float2half(acc1[b]);
    }
}

// ---------------- K6: mma.sync fp16 GEMM, double-buffered, 2 CTAs/SM ------
// B staged via cp.async in the SAME commit group as A chunk 0.
#define OFF_B  0
#define OFF_A0 66560
#define OFF_A1 84992
#define SMEM_MM 103424

__global__ __launch_bounds__(256, 2) void gemm_mm_kernel(
    float* __restrict__ out, int N) {
    extern __shared__ __align__(16) char sm[];
    uint32_t sbase = smem_u32(sm);
    int tid = threadIdx.x, wid = tid >> 5, lid = tid & 31;
    int nb = blockIdx.x * 128;
    int warp_m = (wid & 3) * 32;
    int warp_n = (wid >> 2) * 32;

    // ---- stage B async: 64 rows x 1024 B (no commit; joins A0's group) ----
#pragma unroll
    for (int t = 0; t < 8; t++) {
        int idx = t * 256 + tid;
        int row = idx >> 5;
        int cb = (idx & 31) * 32;
        cp16(sbase + OFF_B + row * 1040 + cb,
             (const char*)g_Bthi + row * 1024 + cb);
        cp16(sbase + OFF_B + row * 1040 + cb + 16,
             (const char*)g_Bthi + row * 1024 + cb + 16);
    }

    auto stageA = [&](int c, uint32_t offA) {
#pragma unroll
        for (int t = 0; t < 2; t++) {
            int idx = t * 256 + tid;
            int row = idx >> 2;
            int cb = (idx & 3) * 32;
            size_t gb = (size_t)(nb + row) * 1024 + (size_t)c * 128 + cb;
            cp16(sbase + offA + row * 144 + cb, (const char*)g_Ahi + gb);
            cp16(sbase + offA + row * 144 + cb + 16, (const char*)g_Ahi + gb + 16);
        }
        CP_COMMIT();
    };

    float acc[2][4][4];
#pragma unroll
    for (int mt = 0; mt < 2; mt++)
#pragma unroll
        for (int nt = 0; nt < 4; nt++)
#pragma unroll
            for (int q = 0; q < 4; q++) acc[mt][nt][q] = 0.f;

    uint32_t a_row0 = (uint32_t)(warp_m + (lid & 15));
    uint32_t a_kb = (uint32_t)(lid & 16);
    uint32_t a_off = a_row0 * 144 + a_kb;
    uint32_t b_row = (uint32_t)(warp_n + (lid & 7) + ((lid >> 4) & 1) * 8);
    uint32_t b_kb = (uint32_t)(((lid >> 3) & 1) * 16);
    uint32_t baddr0 = sbase + OFF_B + b_row * 1040 + b_kb;
    uint32_t baddr1 = baddr0 + 16 * 1040;

    stageA(0, OFF_A0);   // commits group {B, A0}

    for (int c = 0; c < 8; c++) {
        int cur = c & 1;
        if (c < 7) stageA(c + 1, cur ? OFF_A0 : OFF_A1);
        if (c < 7) CP_WAIT(1); else CP_WAIT(0);
        __syncthreads();

        uint32_t ah0 = sbase + (cur ? OFF_A1 : OFF_A0) + a_off;

#pragma unroll
        for (int ks = 0; ks < 4; ks++) {
            uint32_t kb = (uint32_t)(ks * 32);
            uint32_t gkb = (uint32_t)(c * 128) + kb;
            uint32_t ahi[2][4];
            ldsm4(ahi[0], ah0 + kb);
            ldsm4(ahi[1], ah0 + 16 * 144 + kb);
            uint32_t bhp[2][4];
            ldsm4(bhp[0], baddr0 + gkb);
            ldsm4(bhp[1], baddr1 + gkb);
#pragma unroll
            for (int mt = 0; mt < 2; mt++) {
#pragma unroll
                for (int nt = 0; nt < 4; nt++) {
                    const uint32_t* bf = &bhp[nt >> 1][(nt & 1) * 2];
                    mma16816(acc[mt][nt], ahi[mt], bf);
                }
            }
        }
        __syncthreads();
    }

    int trow = lid >> 2, tcol = (lid & 3) * 2;
#pragma unroll
    for (int mt = 0; mt < 2; mt++) {
        int m0 = nb + warp_m + mt * 16 + trow;
#pragma unroll
        for (int nt = 0; nt < 4; nt++) {
            int col = warp_n + nt * 8 + tcol;
            if (m0 < N)
                *(float2*)(out + (size_t)m0 * 64 + col) =
                    make_float2(acc[mt][nt][0], acc[mt][nt][1]);
            if (m0 + 8 < N)
                *(float2*)(out + (size_t)(m0 + 8) * 64 + col) =
                    make_float2(acc[mt][nt][2], acc[mt][nt][3]);
        }
    }
}

// ---------------- launch ----------------
extern "C" void kernel_launch(void* const* d_in, const int* in_sizes, int n_in,
                              void* d_out, int out_size) {
    const float* x = (const float*)d_in[0];
    const void* mask = d_in[1];
    const int* src = (const int*)d_in[2];
    const int* tgt = (const int*)d_in[3];
    const int* et = (const int*)d_in[4];
    const float* bases = (const float*)d_in[5];
    const float* att = (const float*)d_in[6];
    float* out = (float*)d_out;

    int N = in_sizes[1];
    int E = in_sizes[2];
    int nb = (N + 1023) / 1024;

    cudaFuncSetAttribute(gemm_mm_kernel,
                         cudaFuncAttributeMaxDynamicSharedMemorySize, SMEM_MM);

    zero_kernel<<<256, 256>>>(N);
    sniff_kernel<<<256, 256>>>((const unsigned int*)d_in[2], E,
                               (const unsigned int*)d_in[1], N);
    finalize_sniff_kernel<<<1, 1>>>();
    prep_bases_kernel<<<128, 256>>>(bases);
    hist_kernel<<<3200, 256>>>(src, tgt, E);
    scan1_kernel<<<nb, 256>>>(N);
    scan2_kernel<<<1, 256>>>(nb, N);
    scan3_kernel<<<nb, 256>>>(N);
    scatter_kernel<<<3200, 256>>>(src, tgt, et, E);
    agg_kernel<<<(N + 15) / 16, 512>>>(x, mask, att, N);
    gemm_mm_kernel<<<(N + 127) / 128, 256, SMEM_MM>>>(out, N);
}

// round 16
// speedup vs baseline: 1.3118x; 1.0405x over previous
#include <cuda_runtime.h>
#include <cuda_fp16.h>
#include <cstdint>

#define NN 200000
#define NE 800000
#define NPAD 200064   // 1563 * 128

// ---------------- device scratch (no allocations allowed) ----------------
__device__ int g_is64;
__device__ int g_mask_mode;  // 0 = byte bool, 1 = int32, 2 = int64
__device__ unsigned int g_flags[3];
__device__ int g_count[NN];
__device__ int g_off[NN + 1];
__device__ int g_cur[NN];
__device__ int g_bsum[256];
__device__ int g_boff[256];
__device__ unsigned int g_sorted[2 * NE];
__device__ __half g_Ahi[(size_t)NPAD * 512];  // 205 MB
__device__ __half g_Bthi[64 * 512];           // basesT fp16 (n-major, k-contig)

// ---------------- helpers ----------------
__device__ __forceinline__ int ldidx(const int* p, int i, int is64) {
    return is64 ? p[2 * i] : p[i];
}
__device__ __forceinline__ uint32_t smem_u32(const void* p) {
    uint32_t a;
    asm("{ .reg .u64 t; cvta.to.shared.u64 t, %1; cvt.u32.u64 %0, t; }"
        : "=r"(a) : "l"(p));
    return a;
}
__device__ __forceinline__ void ldsm4(uint32_t* r, uint32_t addr) {
    asm volatile("ldmatrix.sync.aligned.m8n8.x4.shared.b16 {%0,%1,%2,%3}, [%4];"
                 : "=r"(r[0]), "=r"(r[1]), "=r"(r[2]), "=r"(r[3]) : "r"(addr));
}
__device__ __forceinline__ void mma16816(float* c, const uint32_t* a,
                                         const uint32_t* b) {
    asm volatile(
        "mma.sync.aligned.m16n8k16.row.col.f32.f16.f16.f32 "
        "{%0,%1,%2,%3}, {%4,%5,%6,%7}, {%8,%9}, {%0,%1,%2,%3};"
        : "+f"(c[0]), "+f"(c[1]), "+f"(c[2]), "+f"(c[3])
        : "r"(a[0]), "r"(a[1]), "r"(a[2]), "r"(a[3]), "r"(b[0]), "r"(b[1]));
}
__device__ __forceinline__ void cp16(uint32_t saddr, const void* gptr) {
    asm volatile("cp.async.cg.shared.global [%0], [%1], 16;"
                 :: "r"(saddr), "l"(gptr) : "memory");
}
#define CP_COMMIT() asm volatile("cp.async.commit_group;" ::: "memory")
#define CP_WAIT(n)  asm volatile("cp.async.wait_group %0;" :: "n"(n) : "memory")

// ---------------- K0a: zero hist + flags + basesT fp16 prep ----------------
__global__ void zero_kernel(const float* __restrict__ bases, int N) {
    int i0 = blockIdx.x * blockDim.x + threadIdx.x;
    if (i0 < 3) g_flags[i0] = 0u;
    // basesT: BT[n][k] = bases[k][n], fp16 (32768 elems, single pass)
    if (i0 < 512 * 64) {
        int n = i0 >> 9, k = i0 & 511;
        g_Bthi[n * 512 + k] = __float2half(bases[k * 64 + n]);
    }
    for (int i = i0; i < N; i += gridDim.x * blockDim.x) g_count[i] = 0;
}

// ---------------- K0b: parallel dtype sniff ----------------
__global__ void sniff_kernel(const unsigned int* idx_words, int n_idx_words,
                             const unsigned int* mask_words, int n_mask) {
    int i0 = blockIdx.x * blockDim.x + threadIdx.x;
    int stride = gridDim.x * blockDim.x;
    unsigned f0 = 0, f1 = 0, f2 = 0;
    for (int i = 1 + 2 * i0; i < n_idx_words; i += 2 * stride)
        f0 |= (idx_words[i] != 0u);
    for (int i = i0; i < n_mask / 4; i += stride)
        f1 |= (mask_words[i] > 1u);
    for (int i = 1 + 2 * i0; i < n_mask / 2; i += 2 * stride)
        f2 |= (mask_words[i] != 0u);
    if (f0) atomicOr(&g_flags[0], 1u);
    if (f1) atomicOr(&g_flags[1], 1u);
    if (f2) atomicOr(&g_flags[2], 1u);
}

__global__ void finalize_sniff_kernel() {
    g_is64 = g_flags[0] ? 0 : 1;
    g_mask_mode = g_flags[1] ? 0 : (g_flags[2] ? 1 : 2);
}

// ---------------- K2: histogram of edge-direction targets ----------------
__global__ void hist_kernel(const int* src, const int* tgt, int E) {
    int is64 = g_is64;
    for (int i = blockIdx.x * blockDim.x + threadIdx.x; i < 2 * E;
         i += gridDim.x * blockDim.x) {
        int t = (i < E) ? ldidx(tgt, i, is64) : ldidx(src, i - E, is64);
        atomicAdd(&g_count[t], 1);
    }
}

// ---------------- K3: multi-block exclusive scan ----------------
__global__ void scan1_kernel(int N) {
    __shared__ int red[256];
    int b = blockIdx.x, t = threadIdx.x;
    int base = b * 1024 + t * 4;
    int s = 0;
#pragma unroll
    for (int j = 0; j < 4; j++) {
        int idx = base + j;
        if (idx < N) s += g_count[idx];
    }
    red[t] = s;
    __syncthreads();
    for (int off = 128; off > 0; off >>= 1) {
        if (t < off) red[t] += red[t + off];
        __syncthreads();
    }
    if (t == 0) g_bsum[b] = red[0];
}

__global__ void scan2_kernel(int nb, int N) {
    __shared__ int ts[256];
    int t = threadIdx.x;
    int v = (t < nb) ? g_bsum[t] : 0;
    ts[t] = v;
    __syncthreads();
    for (int off = 1; off < 256; off <<= 1) {
        int u = (t >= off) ? ts[t - off] : 0;
        __syncthreads();
        ts[t] += u;
        __syncthreads();
    }
    if (t < nb) g_boff[t] = ts[t] - v;
    if (t == 255) g_off[N] = ts[255];
}

__global__ void scan3_kernel(int N) {
    __shared__ int ts[256];
    int b = blockIdx.x, t = threadIdx.x;
    int base = b * 1024 + t * 4;
    int c[4];
    int s = 0;
#pragma unroll
    for (int j = 0; j < 4; j++) {
        int idx = base + j;
        c[j] = (idx < N) ? g_count[idx] : 0;
        s += c[j];
    }
    ts[t] = s;
    __syncthreads();
    for (int off = 1; off < 256; off <<= 1) {
        int u = (t >= off) ? ts[t - off] : 0;
        __syncthreads();
        ts[t] += u;
        __syncthreads();
    }
    int run = ts[t] - s + g_boff[b];
#pragma unroll
    for (int j = 0; j < 4; j++) {
        int idx = base + j;
        if (idx < N) {
            g_off[idx] = run;
            g_cur[idx] = run;
            run += c[j];
        }
    }
}

// ---------------- K4: scatter edges sorted by target ----------------
__global__ void scatter_kernel(const int* src, const int* tgt, const int* et,
                               int E) {
    int is64 = g_is64;
    for (int i = blockIdx.x * blockDim.x + threadIdx.x; i < 2 * E;
         i += gridDim.x * blockDim.x) {
        int e = (i < E) ? i : i - E;
        int s, t;
        if (i < E) { s = ldidx(src, e, is64); t = ldidx(tgt, e, is64); }
        else       { s = ldidx(tgt, e, is64); t = ldidx(src, e, is64); }
        int r = ldidx(et, e, is64);
        int pos = atomicAdd(&g_cur[t], 1);
        g_sorted[pos] = ((unsigned int)s << 4) | (unsigned int)r;
    }
}

// ---------------- K5: aggregation, warp per node, writes fp16 (R9) ----------
__global__ void agg_kernel(const float* __restrict__ x,
                           const void* __restrict__ mask,
                           const float* __restrict__ att, int N) {
    __shared__ __align__(16) float4 att_s[34];
    int tid = threadIdx.x;
    if (tid < 34) att_s[tid] = ((const float4*)att)[tid];
    __syncthreads();

    int warp = tid >> 5, lane = tid & 31;
    int n = blockIdx.x * 8 + warp;
    if (n >= N) return;

    float acc0[8], acc1[8];
#pragma unroll
    for (int b = 0; b < 8; b++) { acc0[b] = 0.f; acc1[b] = 0.f; }

    int beg = g_off[n], end = g_off[n + 1];
    for (int i = beg; i < end; i++) {
        unsigned int p = g_sorted[i];
        int s = (int)(p >> 4);
        int r = (int)(p & 15u);
        float x0 = x[s * 64 + lane];
        float x1 = x[s * 64 + 32 + lane];
        float4 a0 = att_s[r * 2];
        float4 a1 = att_s[r * 2 + 1];
        float ar[8];
        *(float4*)&ar[0] = a0;
        *(float4*)&ar[4] = a1;
#pragma unroll
        for (int b = 0; b < 8; b++) {
            acc0[b] += ar[b] * x0;
            acc1[b] += ar[b] * x1;
        }
    }
    int mm = g_mask_mode;
    int keep;
    if (mm == 0)      keep = ((const unsigned char*)mask)[n];
    else if (mm == 1) keep = ((const int*)mask)[n];
    else              keep = ((const int*)mask)[2 * n];
    if (keep) {
        float x0 = x[n * 64 + lane];
        float x1 = x[n * 64 + 32 + lane];
        float4 a0 = att_s[32];
        float4 a1 = att_s[33];
        float ar[8];
        *(float4*)&ar[0] = a0;
        *(float4*)&ar[4] = a1;
#pragma unroll
        for (int b = 0; b < 8; b++) {
            acc0[b] += ar[b] * x0;
            acc1[b] += ar[b] * x1;
        }
    }
    size_t base = (size_t)n * 512;
#pragma unroll
    for (int b = 0; b < 8; b++) {
        g_Ahi[base + b * 64 + lane]      = __float2half(acc0[b]);
        g_Ahi[base + b * 64 + 32 + lane] = __float2half(acc1[b]);
    }
}

// ---------------- K6: mma.sync fp16 GEMM, double-buffered, 2 CTAs/SM (R9) --
#define OFF_B  0
#define OFF_A0 66560
#define OFF_A1 84992
#define SMEM_MM 103424

__global__ __launch_bounds__(256, 2) void gemm_mm_kernel(
    float* __restrict__ out, int N) {
    extern __shared__ __align__(16) char sm[];
    uint32_t sbase = smem_u32(sm);
    int tid = threadIdx.x, wid = tid >> 5, lid = tid & 31;
    int nb = blockIdx.x * 128;
    int warp_m = (wid & 3) * 32;
    int warp_n = (wid >> 2) * 32;

    // ---- stage B once: 64 rows x 512 k fp16 (synchronous, R9 form) ----
#pragma unroll
    for (int t = 0; t < 8; t++) {
        int idx = t * 256 + tid;
        int row = idx >> 5;
        int cb = (idx & 31) * 32;
        *(uint4*)(sm + OFF_B + row * 1040 + cb) =
            *(const uint4*)((const char*)g_Bthi + row * 1024 + cb);
        *(uint4*)(sm + OFF_B + row * 1040 + cb + 16) =
            *(const uint4*)((const char*)g_Bthi + row * 1024 + cb + 16);
    }

    auto stageA = [&](int c, uint32_t offA) {
#pragma unroll
        for (int t = 0; t < 2; t++) {
            int idx = t * 256 + tid;
            int row = idx >> 2;
            int cb = (idx & 3) * 32;
            size_t gb = (size_t)(nb + row) * 1024 + (size_t)c * 128 + cb;
            cp16(sbase + offA + row * 144 + cb, (const char*)g_Ahi + gb);
            cp16(sbase + offA + row * 144 + cb + 16, (const char*)g_Ahi + gb + 16);
        }
        CP_COMMIT();
    };

    float acc[2][4][4];
#pragma unroll
    for (int mt = 0; mt < 2; mt++)
#pragma unroll
        for (int nt = 0; nt < 4; nt++)
#pragma unroll
            for (int q = 0; q < 4; q++) acc[mt][nt][q] = 0.f;

    uint32_t a_row0 = (uint32_t)(warp_m + (lid & 15));
    uint32_t a_kb = (uint32_t)(lid & 16);
    uint32_t a_off = a_row0 * 144 + a_kb;
    uint32_t b_row = (uint32_t)(warp_n + (lid & 7) + ((lid >> 4) & 1) * 8);
    uint32_t b_kb = (uint32_t)(((lid >> 3) & 1) * 16);
    uint32_t baddr0 = sbase + OFF_B + b_row * 1040 + b_kb;
    uint32_t baddr1 = baddr0 + 16 * 1040;

    stageA(0, OFF_A0);

    for (int c = 0; c < 8; c++) {
        int cur = c & 1;
        if (c < 7) stageA(c + 1, cur ? OFF_A0 : OFF_A1);
        if (c < 7) CP_WAIT(1); else CP_WAIT(0);
        __syncthreads();

        uint32_t ah0 = sbase + (cur ? OFF_A1 : OFF_A0) + a_off;

#pragma unroll
        for (int ks = 0; ks < 4; ks++) {
            uint32_t kb = (uint32_t)(ks * 32);
            uint32_t gkb = (uint32_t)(c * 128) + kb;
            uint32_t ahi[2][4];
            ldsm4(ahi[0], ah0 + kb);
            ldsm4(ahi[1], ah0 + 16 * 144 + kb);
            uint32_t bhp[2][4];
            ldsm4(bhp[0], baddr0 + gkb);
            ldsm4(bhp[1], baddr1 + gkb);
#pragma unroll
            for (int mt = 0; mt < 2; mt++) {
#pragma unroll
                for (int nt = 0; nt < 4; nt++) {
                    const uint32_t* bf = &bhp[nt >> 1][(nt & 1) * 2];
                    mma16816(acc[mt][nt], ahi[mt], bf);
                }
            }
        }
        __syncthreads();
    }

    int trow = lid >> 2, tcol = (lid & 3) * 2;
#pragma unroll
    for (int mt = 0; mt < 2; mt++) {
        int m0 = nb + warp_m + mt * 16 + trow;
#pragma unroll
        for (int nt = 0; nt < 4; nt++) {
            int col = warp_n + nt * 8 + tcol;
            if (m0 < N)
                *(float2*)(out + (size_t)m0 * 64 + col) =
                    make_float2(acc[mt][nt][0], acc[mt][nt][1]);
            if (m0 + 8 < N)
                *(float2*)(out + (size_t)(m0 + 8) * 64 + col) =
                    make_float2(acc[mt][nt][2], acc[mt][nt][3]);
        }
    }
}

// ---------------- launch ----------------
extern "C" void kernel_launch(void* const* d_in, const int* in_sizes, int n_in,
                              void* d_out, int out_size) {
    const float* x = (const float*)d_in[0];
    const void* mask = d_in[1];
    const int* src = (const int*)d_in[2];
    const int* tgt = (const int*)d_in[3];
    const int* et = (const int*)d_in[4];
    const float* bases = (const float*)d_in[5];
    const float* att = (const float*)d_in[6];
    float* out = (float*)d_out;

    int N = in_sizes[1];
    int E = in_sizes[2];
    int nb = (N + 1023) / 1024;

    cudaFuncSetAttribute(gemm_mm_kernel,
                         cudaFuncAttributeMaxDynamicSharedMemorySize, SMEM_MM);

    zero_kernel<<<256, 256>>>(bases, N);
    sniff_kernel<<<256, 256>>>((const unsigned int*)d_in[2], E,
                               (const unsigned int*)d_in[1], N);
    finalize_sniff_kernel<<<1, 1>>>();
    hist_kernel<<<3200, 256>>>(src, tgt, E);
    scan1_kernel<<<nb, 256>>>(N);
    scan2_kernel<<<1, 256>>>(nb, N);
    scan3_kernel<<<nb, 256>>>(N);
    scatter_kernel<<<3200, 256>>>(src, tgt, et, E);
    agg_kernel<<<(N + 7) / 8, 256>>>(x, mask, att, N);
    gemm_mm_kernel<<<(N + 127) / 128, 256, SMEM_MM>>>(out, N);
}